// round 1
// baseline (speedup 1.0000x reference)
#include <cuda_runtime.h>
#include <math.h>
#include <stdint.h>

// Shapes
#define BATCH   32
#define SLEN    576          // 24*24 patches
#define EMB_    512
#define NHEAD   8
#define HD      64
#define TOK     (BATCH*SLEN) // 18432
#define IMGW    384
#define KCONV   768          // 3*16*16

// -------- scratch (device globals; no allocation allowed) --------
__device__ float g_h  [TOK*EMB_];   // patch embeddings  [tok][512]
__device__ float g_hq [TOK*EMB_];   // hq = h4 @ G       (per head view [tok*8][64])
__device__ float g_ctx[TOK*EMB_];   // att @ h4          [tok][512]
__device__ float g_Gt [HD*HD];      // Gt[d'][d] = 0.125 * sum_e wq[e,d]*wk[e,d']
__device__ float g_WvoT[EMB_*EMB_]; // WvoT[f][h*64+d] = sum_e wv[e,d]*wo[f,h*64+e]

// =================================================================
// Precompute folded weight matrices
// =================================================================
__global__ void prep_G(const float* __restrict__ wq, const float* __restrict__ wk) {
    int dp = blockIdx.x;   // d' (output index of hq)
    int d  = threadIdx.x;  // d  (input index)
    float s = 0.f;
    #pragma unroll 8
    for (int e = 0; e < 64; e++) s += wq[e*64 + d] * wk[e*64 + dp];
    g_Gt[dp*64 + d] = 0.125f * s;  // fold 1/sqrt(64)
}

__global__ void prep_Wvo(const float* __restrict__ wv, const float* __restrict__ wo) {
    int f  = blockIdx.x;
    int hd = threadIdx.x;
    int h  = hd >> 6, d = hd & 63;
    float s = 0.f;
    #pragma unroll 8
    for (int e = 0; e < 64; e++) s += wv[e*64 + d] * wo[(size_t)f*512 + h*64 + e];
    g_WvoT[(size_t)f*512 + hd] = s;
}

// =================================================================
// Conv patch embedding as implicit-im2col GEMM:
//   h[m][n] = sum_k patch(m)[k] * conv_w[n][k] + conv_b[n]
//   M=18432, N=512, K=768.  BM=BN=128, BK=8, 8x8 microtile, 256 thr.
// =================================================================
__global__ __launch_bounds__(256) void conv_gemm(const float* __restrict__ x,
                                                 const float* __restrict__ w,
                                                 const float* __restrict__ bias) {
    __shared__ float As[8][128];
    __shared__ float Bs[8][128];
    const int tid = threadIdx.x;
    const int tx = tid & 15, ty = tid >> 4;
    const int m0 = blockIdx.y * 128, n0 = blockIdx.x * 128;

    // A loader: each thread owns one tile-row (of 128) and half of BK=8 (float4)
    const int row = tid >> 1;
    const int kq  = (tid & 1) * 4;
    const int m   = m0 + row;
    const int bb  = m / 576, p = m % 576;
    const int py  = p / 24,  px = p % 24;
    const float* abase = x + (size_t)bb*3*IMGW*IMGW + (size_t)(py*16)*IMGW + px*16 + kq;
    const float* bbase = w + (size_t)(n0 + row)*KCONV + kq;

    float acc[8][8] = {};
    for (int k0 = 0; k0 < KCONV; k0 += 8) {
        const int c = k0 >> 8, rem = k0 & 255;
        const int dy = rem >> 4, dx0 = rem & 15;      // dx0 in {0,8}
        float4 fa = *(const float4*)(abase + (size_t)c*(IMGW*IMGW) + dy*IMGW + dx0);
        float4 fb = *(const float4*)(bbase + k0);
        __syncthreads();
        As[kq+0][row]=fa.x; As[kq+1][row]=fa.y; As[kq+2][row]=fa.z; As[kq+3][row]=fa.w;
        Bs[kq+0][row]=fb.x; Bs[kq+1][row]=fb.y; Bs[kq+2][row]=fb.z; Bs[kq+3][row]=fb.w;
        __syncthreads();
        #pragma unroll
        for (int k = 0; k < 8; k++) {
            float a_[8], b_[8];
            *(float4*)&a_[0] = *(const float4*)&As[k][ty*8];
            *(float4*)&a_[4] = *(const float4*)&As[k][ty*8+4];
            *(float4*)&b_[0] = *(const float4*)&Bs[k][tx*8];
            *(float4*)&b_[4] = *(const float4*)&Bs[k][tx*8+4];
            #pragma unroll
            for (int i = 0; i < 8; i++)
                #pragma unroll
                for (int j = 0; j < 8; j++)
                    acc[i][j] = fmaf(a_[i], b_[j], acc[i][j]);
        }
    }
    #pragma unroll
    for (int i = 0; i < 8; i++) {
        const int mm = m0 + ty*8 + i;
        #pragma unroll
        for (int j = 0; j < 8; j += 4) {
            const int nn = n0 + tx*8 + j;
            float4 f;
            f.x = acc[i][j+0] + bias[nn+0];
            f.y = acc[i][j+1] + bias[nn+1];
            f.z = acc[i][j+2] + bias[nn+2];
            f.w = acc[i][j+3] + bias[nn+3];
            *(float4*)(g_h + (size_t)mm*EMB_ + nn) = f;
        }
    }
}

// =================================================================
// Q projection (folded): hq = h4 @ G.   M=147456, N=64, K=64.
//   BM=128, BN=64, BK=16, 8x4 microtile, 256 thr.
// =================================================================
__global__ __launch_bounds__(256) void hq_gemm() {
    __shared__ float As[16][128];
    __shared__ float Bs[16][64];
    const int tid = threadIdx.x;
    const int tx = tid & 15, ty = tid >> 4;
    const int m0 = blockIdx.y * 128;
    const int arow = tid >> 2;           // 0..63
    const int akq  = (tid & 3) * 4;

    float acc[8][4] = {};
    for (int k0 = 0; k0 < 64; k0 += 16) {
        float4 fa0 = *(const float4*)(g_h + (size_t)(m0 + arow     )*64 + k0 + akq);
        float4 fa1 = *(const float4*)(g_h + (size_t)(m0 + arow + 64)*64 + k0 + akq);
        float4 fb  = *(const float4*)(g_Gt + (size_t)arow*64 + k0 + akq);
        __syncthreads();
        As[akq+0][arow   ]=fa0.x; As[akq+1][arow   ]=fa0.y; As[akq+2][arow   ]=fa0.z; As[akq+3][arow   ]=fa0.w;
        As[akq+0][arow+64]=fa1.x; As[akq+1][arow+64]=fa1.y; As[akq+2][arow+64]=fa1.z; As[akq+3][arow+64]=fa1.w;
        Bs[akq+0][arow]=fb.x; Bs[akq+1][arow]=fb.y; Bs[akq+2][arow]=fb.z; Bs[akq+3][arow]=fb.w;
        __syncthreads();
        #pragma unroll
        for (int k = 0; k < 16; k++) {
            float a_[8], b_[4];
            *(float4*)&a_[0] = *(const float4*)&As[k][ty*8];
            *(float4*)&a_[4] = *(const float4*)&As[k][ty*8+4];
            *(float4*)&b_[0] = *(const float4*)&Bs[k][tx*4];
            #pragma unroll
            for (int i = 0; i < 8; i++)
                #pragma unroll
                for (int j = 0; j < 4; j++)
                    acc[i][j] = fmaf(a_[i], b_[j], acc[i][j]);
        }
    }
    #pragma unroll
    for (int i = 0; i < 8; i++) {
        float4 f; f.x=acc[i][0]; f.y=acc[i][1]; f.z=acc[i][2]; f.w=acc[i][3];
        *(float4*)(g_hq + (size_t)(m0 + ty*8 + i)*64 + tx*4) = f;
    }
}

// =================================================================
// Flash-style attention, fp32.  Block = (q-tile 64, head, batch).
// K-tile and V-tile are the SAME data (raw h) -> one smem tile.
// 256 threads, 4x4 microtiles for both QK^T and P@V.
// =================================================================
#define ATTN_SMEM ((64*64 + 64*65 + 64*65) * 4)

__global__ __launch_bounds__(256) void attn_kernel() {
    extern __shared__ float sm[];
    float* Qs  = sm;              // [64][64]
    float* KVs = sm + 64*64;      // [64][65] padded
    float* Ps  = KVs + 64*65;     // [64][65] padded

    const int qt = blockIdx.x, hh = blockIdx.y, b = blockIdx.z;
    const int tid = threadIdx.x;
    const int tx = tid & 15, ty = tid >> 4;
    const size_t rowbase = (size_t)(b*SLEN)*EMB_ + hh*HD;

    {   // load Q tile (hq)
        const float* qb = g_hq + rowbase + (size_t)(qt*64)*EMB_;
        #pragma unroll
        for (int i = 0; i < 4; i++) {
            int v = tid + i*256;
            int r = v >> 4, cq = (v & 15) * 4;
            float4 f = *(const float4*)(qb + (size_t)r*EMB_ + cq);
            *(float4*)(Qs + r*64 + cq) = f;
        }
    }

    float acc[4][4] = {};
    float mrow[4], lrow[4];
    #pragma unroll
    for (int i = 0; i < 4; i++) { mrow[i] = -3.0e38f; lrow[i] = 0.f; }

    for (int kt = 0; kt < 9; kt++) {
        const float* kb = g_h + rowbase + (size_t)(kt*64)*EMB_;
        float4 ld[4];
        #pragma unroll
        for (int i = 0; i < 4; i++) {
            int v = tid + i*256;
            int r = v >> 4, cq = (v & 15) * 4;
            ld[i] = *(const float4*)(kb + (size_t)r*EMB_ + cq);
        }
        __syncthreads();   // prior iteration done reading KVs/Ps
        #pragma unroll
        for (int i = 0; i < 4; i++) {
            int v = tid + i*256;
            int r = v >> 4, cq = (v & 15) * 4;
            KVs[r*65+cq+0]=ld[i].x; KVs[r*65+cq+1]=ld[i].y;
            KVs[r*65+cq+2]=ld[i].z; KVs[r*65+cq+3]=ld[i].w;
        }
        __syncthreads();

        // scores: s[i][j] = dot(Q[ty*4+i,:], K[tx*4+j,:])   (scale folded into G)
        float s[4][4] = {};
        #pragma unroll
        for (int c = 0; c < 64; c++) {
            float a_[4], b_[4];
            #pragma unroll
            for (int i = 0; i < 4; i++) a_[i] = Qs[(ty*4+i)*64 + c];
            #pragma unroll
            for (int j = 0; j < 4; j++) b_[j] = KVs[(tx*4+j)*65 + c];
            #pragma unroll
            for (int i = 0; i < 4; i++)
                #pragma unroll
                for (int j = 0; j < 4; j++)
                    s[i][j] = fmaf(a_[i], b_[j], s[i][j]);
        }

        // online softmax (row group = 16 lanes sharing ty)
        #pragma unroll
        for (int i = 0; i < 4; i++) {
            float mx = fmaxf(fmaxf(s[i][0], s[i][1]), fmaxf(s[i][2], s[i][3]));
            mx = fmaxf(mx, __shfl_xor_sync(0xffffffffu, mx, 1));
            mx = fmaxf(mx, __shfl_xor_sync(0xffffffffu, mx, 2));
            mx = fmaxf(mx, __shfl_xor_sync(0xffffffffu, mx, 4));
            mx = fmaxf(mx, __shfl_xor_sync(0xffffffffu, mx, 8));
            float mnew  = fmaxf(mrow[i], mx);
            float alpha = __expf(mrow[i] - mnew);
            mrow[i] = mnew;
            float ps = 0.f;
            #pragma unroll
            for (int j = 0; j < 4; j++) { float pp = __expf(s[i][j] - mnew); s[i][j] = pp; ps += pp; }
            ps += __shfl_xor_sync(0xffffffffu, ps, 1);
            ps += __shfl_xor_sync(0xffffffffu, ps, 2);
            ps += __shfl_xor_sync(0xffffffffu, ps, 4);
            ps += __shfl_xor_sync(0xffffffffu, ps, 8);
            lrow[i] = lrow[i]*alpha + ps;
            #pragma unroll
            for (int j = 0; j < 4; j++) acc[i][j] *= alpha;
            #pragma unroll
            for (int j = 0; j < 4; j++) Ps[(ty*4+i)*65 + tx*4 + j] = s[i][j];
        }
        __syncthreads();

        // acc[i][d] += sum_c P[i][c] * V[c][d]   (V == KVs)
        #pragma unroll
        for (int c = 0; c < 64; c++) {
            float p_[4], v_[4];
            #pragma unroll
            for (int i = 0; i < 4; i++) p_[i] = Ps[(ty*4+i)*65 + c];
            #pragma unroll
            for (int j = 0; j < 4; j++) v_[j] = KVs[c*65 + tx*4 + j];
            #pragma unroll
            for (int i = 0; i < 4; i++)
                #pragma unroll
                for (int j = 0; j < 4; j++)
                    acc[i][j] = fmaf(p_[i], v_[j], acc[i][j]);
        }
    }

    float* ob = g_ctx + rowbase + (size_t)(qt*64)*EMB_;
    #pragma unroll
    for (int i = 0; i < 4; i++) {
        int r = ty*4 + i;
        float inv = 1.0f / lrow[i];
        float4 f;
        f.x = acc[i][0]*inv; f.y = acc[i][1]*inv; f.z = acc[i][2]*inv; f.w = acc[i][3]*inv;
        *(float4*)(ob + (size_t)r*EMB_ + tx*4) = f;
    }
}

// =================================================================
// Output projection (folded Wv into Wo): out = ctx @ WvoT^T + bo
//   M=18432, N=512, K=512.  Same 128x128x8 shape.
// =================================================================
__global__ __launch_bounds__(256) void proj_gemm(const float* __restrict__ bias,
                                                 float* __restrict__ C) {
    __shared__ float As[8][128];
    __shared__ float Bs[8][128];
    const int tid = threadIdx.x;
    const int tx = tid & 15, ty = tid >> 4;
    const int m0 = blockIdx.y * 128, n0 = blockIdx.x * 128;
    const int row = tid >> 1;
    const int kq  = (tid & 1) * 4;
    const float* abase = g_ctx  + (size_t)(m0 + row)*EMB_ + kq;
    const float* bbase = g_WvoT + (size_t)(n0 + row)*EMB_ + kq;

    float acc[8][8] = {};
    for (int k0 = 0; k0 < EMB_; k0 += 8) {
        float4 fa = *(const float4*)(abase + k0);
        float4 fb = *(const float4*)(bbase + k0);
        __syncthreads();
        As[kq+0][row]=fa.x; As[kq+1][row]=fa.y; As[kq+2][row]=fa.z; As[kq+3][row]=fa.w;
        Bs[kq+0][row]=fb.x; Bs[kq+1][row]=fb.y; Bs[kq+2][row]=fb.z; Bs[kq+3][row]=fb.w;
        __syncthreads();
        #pragma unroll
        for (int k = 0; k < 8; k++) {
            float a_[8], b_[8];
            *(float4*)&a_[0] = *(const float4*)&As[k][ty*8];
            *(float4*)&a_[4] = *(const float4*)&As[k][ty*8+4];
            *(float4*)&b_[0] = *(const float4*)&Bs[k][tx*8];
            *(float4*)&b_[4] = *(const float4*)&Bs[k][tx*8+4];
            #pragma unroll
            for (int i = 0; i < 8; i++)
                #pragma unroll
                for (int j = 0; j < 8; j++)
                    acc[i][j] = fmaf(a_[i], b_[j], acc[i][j]);
        }
    }
    #pragma unroll
    for (int i = 0; i < 8; i++) {
        const int mm = m0 + ty*8 + i;
        #pragma unroll
        for (int j = 0; j < 8; j += 4) {
            const int nn = n0 + tx*8 + j;
            float4 f;
            f.x = acc[i][j+0] + bias[nn+0];
            f.y = acc[i][j+1] + bias[nn+1];
            f.z = acc[i][j+2] + bias[nn+2];
            f.w = acc[i][j+3] + bias[nn+3];
            *(float4*)(C + (size_t)mm*EMB_ + nn) = f;
        }
    }
}

// =================================================================
extern "C" void kernel_launch(void* const* d_in, const int* in_sizes, int n_in,
                              void* d_out, int out_size) {
    (void)in_sizes; (void)n_in; (void)out_size;
    const float* x      = (const float*)d_in[0];
    const float* conv_w = (const float*)d_in[1];
    const float* conv_b = (const float*)d_in[2];
    const float* wq     = (const float*)d_in[3];
    const float* wk     = (const float*)d_in[4];
    const float* wv     = (const float*)d_in[5];
    const float* wo     = (const float*)d_in[6];
    const float* bo     = (const float*)d_in[7];
    float* out = (float*)d_out;

    cudaFuncSetAttribute(attn_kernel, cudaFuncAttributeMaxDynamicSharedMemorySize, ATTN_SMEM);

    prep_G  <<<64, 64>>>(wq, wk);
    prep_Wvo<<<512, 512>>>(wv, wo);
    conv_gemm<<<dim3(4, 144), 256>>>(x, conv_w, conv_b);
    hq_gemm  <<<dim3(1, 1152), 256>>>();
    attn_kernel<<<dim3(9, NHEAD, BATCH), 256, ATTN_SMEM>>>();
    proj_gemm<<<dim3(4, 144), 256>>>(bo, out);
}

// round 3
// speedup vs baseline: 2.7633x; 2.7633x over previous
#include <cuda_runtime.h>
#include <math.h>
#include <stdint.h>

// Shapes
#define BATCH   32
#define SLEN    576
#define EMB_    512
#define NHEAD   8
#define HD      64
#define TOK     (BATCH*SLEN) // 18432
#define IMGW    384
#define KCONV   768

// -------- scratch (device globals) --------
__device__ float g_h  [TOK*EMB_];   // patch embeddings
__device__ float g_hq [TOK*EMB_];   // h @ G (per-head q)
__device__ float g_ctx[TOK*EMB_];   // att @ h
__device__ float g_Gt [HD*HD];
__device__ float g_WvoT[EMB_*EMB_];

// ---------------- tf32 helpers ----------------
__device__ __forceinline__ uint32_t f2tf(float x) {
    uint32_t r; asm("cvt.rna.tf32.f32 %0, %1;" : "=r"(r) : "f"(x)); return r;
}
__device__ __forceinline__ void mma_tf32(float* c, const uint32_t* a, uint32_t b0, uint32_t b1) {
    asm volatile(
        "mma.sync.aligned.m16n8k8.row.col.f32.tf32.tf32.f32 "
        "{%0,%1,%2,%3}, {%4,%5,%6,%7}, {%8,%9}, {%0,%1,%2,%3};\n"
        : "+f"(c[0]), "+f"(c[1]), "+f"(c[2]), "+f"(c[3])
        : "r"(a[0]), "r"(a[1]), "r"(a[2]), "r"(a[3]), "r"(b0), "r"(b1));
}
__device__ __forceinline__ void cp_async16(void* smem, const void* gmem) {
    uint32_t s = (uint32_t)__cvta_generic_to_shared(smem);
    asm volatile("cp.async.cg.shared.global [%0], [%1], 16;\n" :: "r"(s), "l"(gmem));
}
#define CP_COMMIT() asm volatile("cp.async.commit_group;\n")
#define CP_WAIT(n)  asm volatile("cp.async.wait_group %0;\n" :: "n"(n))

// =================================================================
// Weight folding preps (tiny)
// =================================================================
__global__ void prep_G(const float* __restrict__ wq, const float* __restrict__ wk) {
    int dp = blockIdx.x, d = threadIdx.x;
    float s = 0.f;
    #pragma unroll 8
    for (int e = 0; e < 64; e++) s += wq[e*64 + d] * wk[e*64 + dp];
    g_Gt[dp*64 + d] = 0.125f * s;
}
__global__ void prep_Wvo(const float* __restrict__ wv, const float* __restrict__ wo) {
    int f = blockIdx.x, hd = threadIdx.x;
    int h = hd >> 6, d = hd & 63;
    float s = 0.f;
    #pragma unroll 8
    for (int e = 0; e < 64; e++) s += wv[e*64 + d] * wo[(size_t)f*512 + h*64 + e];
    g_WvoT[(size_t)f*512 + hd] = s;
}

// =================================================================
// hq = h4 @ G (fp32 SIMT; memory-bound small kernel)
// =================================================================
__global__ __launch_bounds__(256) void hq_gemm() {
    __shared__ float As[16][128];
    __shared__ float Bs[16][64];
    const int tid = threadIdx.x;
    const int tx = tid & 15, ty = tid >> 4;
    const int m0 = blockIdx.y * 128;
    const int arow = tid >> 2;
    const int akq  = (tid & 3) * 4;

    float acc[8][4] = {};
    for (int k0 = 0; k0 < 64; k0 += 16) {
        float4 fa0 = *(const float4*)(g_h + (size_t)(m0 + arow     )*64 + k0 + akq);
        float4 fa1 = *(const float4*)(g_h + (size_t)(m0 + arow + 64)*64 + k0 + akq);
        float4 fb  = *(const float4*)(g_Gt + (size_t)arow*64 + k0 + akq);
        __syncthreads();
        As[akq+0][arow   ]=fa0.x; As[akq+1][arow   ]=fa0.y; As[akq+2][arow   ]=fa0.z; As[akq+3][arow   ]=fa0.w;
        As[akq+0][arow+64]=fa1.x; As[akq+1][arow+64]=fa1.y; As[akq+2][arow+64]=fa1.z; As[akq+3][arow+64]=fa1.w;
        Bs[akq+0][arow]=fb.x; Bs[akq+1][arow]=fb.y; Bs[akq+2][arow]=fb.z; Bs[akq+3][arow]=fb.w;
        __syncthreads();
        #pragma unroll
        for (int k = 0; k < 16; k++) {
            float a_[8], b_[4];
            *(float4*)&a_[0] = *(const float4*)&As[k][ty*8];
            *(float4*)&a_[4] = *(const float4*)&As[k][ty*8+4];
            *(float4*)&b_[0] = *(const float4*)&Bs[k][tx*4];
            #pragma unroll
            for (int i = 0; i < 8; i++)
                #pragma unroll
                for (int j = 0; j < 4; j++)
                    acc[i][j] = fmaf(a_[i], b_[j], acc[i][j]);
        }
    }
    #pragma unroll
    for (int i = 0; i < 8; i++) {
        float4 f; f.x=acc[i][0]; f.y=acc[i][1]; f.z=acc[i][2]; f.w=acc[i][3];
        *(float4*)(g_hq + (size_t)(m0 + ty*8 + i)*64 + tx*4) = f;
    }
}

// =================================================================
// tf32 MMA GEMM: C[m][n] = A[m][:] . B[n][:] + bias[n]
//   BM=128 BN=128 BK=32, 256 thr (8 warps, 2x4), warp tile 64x32.
//   CONV=true: A = implicit im2col of x, B = conv_w, C = g_h
//   CONV=false: A = g_ctx, B = g_WvoT, C = out
// =================================================================
#define GEMM_SMEM (2*128*36*2*4)   // 73728 B

template<bool CONV>
__global__ __launch_bounds__(256) void mma_gemm(const float* __restrict__ Ain,
                                                const float* __restrict__ Bin,
                                                const float* __restrict__ bias,
                                                float* __restrict__ Cout, int K) {
    extern __shared__ float sm[];
    float* As = sm;                 // [2][128][36]
    float* Bs = sm + 2*128*36;      // [2][128][36]

    const int tid = threadIdx.x;
    const int lane = tid & 31;
    const int w = tid >> 5, wm = w & 1, wn = w >> 1;
    const int g = lane >> 2, tig = lane & 3;
    const int m0 = blockIdx.y * 128, n0 = blockIdx.x * 128;

    const float* A = CONV ? Ain : g_ctx;
    const float* B = CONV ? Bin : g_WvoT;

    // loader precompute: 4 chunks per thread, v = tid + i*256
    int lrow[4], lkc[4];
    const float* abase[4];
    const float* bbase[4];
    #pragma unroll
    for (int i = 0; i < 4; i++) {
        int v = tid + i*256;
        int row = v >> 3, kc = v & 7;
        lrow[i] = row; lkc[i] = kc;
        if (CONV) {
            int m = m0 + row;
            int bb = m / 576, p = m % 576;
            int py = p / 24, px = p % 24;
            abase[i] = A + (size_t)bb*3*IMGW*IMGW + (size_t)(py*16)*IMGW + px*16;
        } else {
            abase[i] = A + (size_t)(m0 + row)*512 + kc*4;
        }
        bbase[i] = B + (size_t)(n0 + row)*K + kc*4;
    }

    auto load_tiles = [&](int buf, int k0) {
        #pragma unroll
        for (int i = 0; i < 4; i++) {
            const float* ga;
            if (CONV) {
                int kg = k0 + lkc[i]*4;
                int c = kg >> 8, rem = kg & 255;
                int dy = rem >> 4, dx = rem & 15;
                ga = abase[i] + (size_t)c*(IMGW*IMGW) + dy*IMGW + dx;
            } else {
                ga = abase[i] + k0;
            }
            cp_async16(&As[buf*4608 + lrow[i]*36 + lkc[i]*4], ga);
            cp_async16(&Bs[buf*4608 + lrow[i]*36 + lkc[i]*4], bbase[i] + k0);
        }
    };

    float acc[4][4][4] = {};

    load_tiles(0, 0);
    CP_COMMIT();
    const int nk = K / 32;
    for (int t = 0; t < nk; t++) {
        int buf = t & 1;
        if (t + 1 < nk) load_tiles(buf ^ 1, (t+1)*32);
        CP_COMMIT();
        CP_WAIT(1);
        __syncthreads();

        const float* Ab = &As[buf*4608];
        const float* Bb = &Bs[buf*4608];
        #pragma unroll
        for (int ks = 0; ks < 4; ks++) {
            int k = ks * 8;
            uint32_t af[4][4], bf[4][2];
            #pragma unroll
            for (int i = 0; i < 4; i++) {
                int r = wm*64 + i*16 + g;
                af[i][0] = f2tf(Ab[(r  )*36 + k + tig]);
                af[i][1] = f2tf(Ab[(r+8)*36 + k + tig]);
                af[i][2] = f2tf(Ab[(r  )*36 + k + tig + 4]);
                af[i][3] = f2tf(Ab[(r+8)*36 + k + tig + 4]);
            }
            #pragma unroll
            for (int j = 0; j < 4; j++) {
                int n = wn*32 + j*8 + g;
                bf[j][0] = f2tf(Bb[n*36 + k + tig]);
                bf[j][1] = f2tf(Bb[n*36 + k + tig + 4]);
            }
            #pragma unroll
            for (int i = 0; i < 4; i++)
                #pragma unroll
                for (int j = 0; j < 4; j++)
                    mma_tf32(acc[i][j], af[i], bf[j][0], bf[j][1]);
        }
        __syncthreads();
    }

    float* C = CONV ? g_h : Cout;
    #pragma unroll
    for (int i = 0; i < 4; i++) {
        int r = m0 + wm*64 + i*16 + g;
        #pragma unroll
        for (int j = 0; j < 4; j++) {
            int cc = n0 + wn*32 + j*8 + tig*2;
            float2 v0 = make_float2(acc[i][j][0] + bias[cc], acc[i][j][1] + bias[cc+1]);
            float2 v1 = make_float2(acc[i][j][2] + bias[cc], acc[i][j][3] + bias[cc+1]);
            *(float2*)&C[(size_t)r*512 + cc] = v0;
            *(float2*)&C[(size_t)(r+8)*512 + cc] = v1;
        }
    }
}

// =================================================================
// Flash attention, tf32 MMA.  Block = 96 q-rows (6 warps x 16), head, batch.
// Q fragments register-resident; K/V = same smem tile (raw h); P via smem.
// =================================================================
#define ATS 72
#define ATTN_SMEM ((96*ATS + 2*64*ATS + 96*ATS)*4)   // 92160 B

__global__ __launch_bounds__(192) void attn_mma() {
    extern __shared__ float sm[];
    float* Qs  = sm;                    // [96][72]
    float* KVs = Qs + 96*ATS;           // [2][64][72]
    float* Ps  = KVs + 2*64*ATS;        // [96][72]

    const int qt = blockIdx.x, hh = blockIdx.y, b = blockIdx.z;
    const int tid = threadIdx.x;
    const int w = tid >> 5, lane = tid & 31;
    const int g = lane >> 2, tig = lane & 3;
    const size_t rowbase = (size_t)(b*SLEN)*EMB_ + hh*HD;

    auto loadKV = [&](int buf, int kt) {
        const float* kb = g_h + rowbase + (size_t)(kt*64)*EMB_;
        for (int v = tid; v < 64*16; v += 192) {
            int r = v >> 4, cq = (v & 15) * 4;
            cp_async16(&KVs[buf*64*ATS + r*ATS + cq], kb + (size_t)r*EMB_ + cq);
        }
    };

    loadKV(0, 0);
    CP_COMMIT();

    {   // load Q tile
        const float* qb = g_hq + rowbase + (size_t)(qt*96)*EMB_;
        for (int v = tid; v < 96*16; v += 192) {
            int r = v >> 4, cq = (v & 15) * 4;
            float4 f = *(const float4*)(qb + (size_t)r*EMB_ + cq);
            *(float4*)(Qs + r*ATS + cq) = f;
        }
    }
    __syncthreads();

    // preload Q fragments for all 8 k-steps (register resident)
    uint32_t aq[8][4];
    {
        int r = w*16 + g;
        #pragma unroll
        for (int ks = 0; ks < 8; ks++) {
            int k = ks*8;
            aq[ks][0] = f2tf(Qs[(r  )*ATS + k + tig]);
            aq[ks][1] = f2tf(Qs[(r+8)*ATS + k + tig]);
            aq[ks][2] = f2tf(Qs[(r  )*ATS + k + tig + 4]);
            aq[ks][3] = f2tf(Qs[(r+8)*ATS + k + tig + 4]);
        }
    }

    float oacc[8][4] = {};
    float m0r = -3.0e38f, m1r = -3.0e38f, l0 = 0.f, l1 = 0.f;
    const int r0 = w*16 + g, r1 = r0 + 8;

    for (int kt = 0; kt < 9; kt++) {
        int buf = kt & 1;
        CP_WAIT(0);
        __syncthreads();                      // KV[buf] ready; prev PV done

        if (kt + 1 < 9) { loadKV(buf ^ 1, kt + 1); CP_COMMIT(); }

        const float* KV = &KVs[buf*64*ATS];

        // ---- S = Q K^T ----
        float sacc[8][4] = {};
        #pragma unroll
        for (int ks = 0; ks < 8; ks++) {
            int k = ks*8;
            uint32_t bf[8][2];
            #pragma unroll
            for (int j = 0; j < 8; j++) {
                int l = j*8 + g;
                bf[j][0] = f2tf(KV[l*ATS + k + tig]);
                bf[j][1] = f2tf(KV[l*ATS + k + tig + 4]);
            }
            #pragma unroll
            for (int j = 0; j < 8; j++)
                mma_tf32(sacc[j], aq[ks], bf[j][0], bf[j][1]);
        }

        // ---- online softmax (rows r0, r1 per thread-quad) ----
        float mx0 = -3.0e38f, mx1 = -3.0e38f;
        #pragma unroll
        for (int j = 0; j < 8; j++) {
            mx0 = fmaxf(mx0, fmaxf(sacc[j][0], sacc[j][1]));
            mx1 = fmaxf(mx1, fmaxf(sacc[j][2], sacc[j][3]));
        }
        mx0 = fmaxf(mx0, __shfl_xor_sync(0xffffffffu, mx0, 1));
        mx0 = fmaxf(mx0, __shfl_xor_sync(0xffffffffu, mx0, 2));
        mx1 = fmaxf(mx1, __shfl_xor_sync(0xffffffffu, mx1, 1));
        mx1 = fmaxf(mx1, __shfl_xor_sync(0xffffffffu, mx1, 2));

        float mn0 = fmaxf(m0r, mx0), mn1 = fmaxf(m1r, mx1);
        float al0 = __expf(m0r - mn0), al1 = __expf(m1r - mn1);
        m0r = mn0; m1r = mn1;

        float s0 = 0.f, s1 = 0.f;
        #pragma unroll
        for (int j = 0; j < 8; j++) {
            float p0 = __expf(sacc[j][0] - mn0);
            float p1 = __expf(sacc[j][1] - mn0);
            float p2 = __expf(sacc[j][2] - mn1);
            float p3 = __expf(sacc[j][3] - mn1);
            s0 += p0 + p1; s1 += p2 + p3;
            Ps[r0*ATS + j*8 + tig*2    ] = p0;
            Ps[r0*ATS + j*8 + tig*2 + 1] = p1;
            Ps[r1*ATS + j*8 + tig*2    ] = p2;
            Ps[r1*ATS + j*8 + tig*2 + 1] = p3;
        }
        s0 += __shfl_xor_sync(0xffffffffu, s0, 1);
        s0 += __shfl_xor_sync(0xffffffffu, s0, 2);
        s1 += __shfl_xor_sync(0xffffffffu, s1, 1);
        s1 += __shfl_xor_sync(0xffffffffu, s1, 2);
        l0 = l0*al0 + s0; l1 = l1*al1 + s1;
        #pragma unroll
        for (int j = 0; j < 8; j++) {
            oacc[j][0] *= al0; oacc[j][1] *= al0;
            oacc[j][2] *= al1; oacc[j][3] *= al1;
        }
        __syncwarp();   // P rows of this warp written by this warp only

        // ---- O += P V ----
        #pragma unroll
        for (int ks = 0; ks < 8; ks++) {
            int k = ks*8;
            uint32_t ap[4];
            ap[0] = f2tf(Ps[r0*ATS + k + tig]);
            ap[1] = f2tf(Ps[r1*ATS + k + tig]);
            ap[2] = f2tf(Ps[r0*ATS + k + tig + 4]);
            ap[3] = f2tf(Ps[r1*ATS + k + tig + 4]);
            #pragma unroll
            for (int j = 0; j < 8; j++) {
                int d = j*8 + g;
                uint32_t b0 = f2tf(KV[(k + tig    )*ATS + d]);
                uint32_t b1 = f2tf(KV[(k + tig + 4)*ATS + d]);
                mma_tf32(oacc[j], ap, b0, b1);
            }
        }
    }

    float inv0 = 1.0f / l0, inv1 = 1.0f / l1;
    float* ob = g_ctx + rowbase + (size_t)(qt*96)*EMB_;
    #pragma unroll
    for (int j = 0; j < 8; j++) {
        int d = j*8 + tig*2;
        *(float2*)&ob[(size_t)r0*EMB_ + d] = make_float2(oacc[j][0]*inv0, oacc[j][1]*inv0);
        *(float2*)&ob[(size_t)r1*EMB_ + d] = make_float2(oacc[j][2]*inv1, oacc[j][3]*inv1);
    }
}

// =================================================================
extern "C" void kernel_launch(void* const* d_in, const int* in_sizes, int n_in,
                              void* d_out, int out_size) {
    (void)in_sizes; (void)n_in; (void)out_size;
    const float* x      = (const float*)d_in[0];
    const float* conv_w = (const float*)d_in[1];
    const float* conv_b = (const float*)d_in[2];
    const float* wq     = (const float*)d_in[3];
    const float* wk     = (const float*)d_in[4];
    const float* wv     = (const float*)d_in[5];
    const float* wo     = (const float*)d_in[6];
    const float* bo     = (const float*)d_in[7];
    float* out = (float*)d_out;

    cudaFuncSetAttribute(mma_gemm<true>,  cudaFuncAttributeMaxDynamicSharedMemorySize, GEMM_SMEM);
    cudaFuncSetAttribute(mma_gemm<false>, cudaFuncAttributeMaxDynamicSharedMemorySize, GEMM_SMEM);
    cudaFuncSetAttribute(attn_mma, cudaFuncAttributeMaxDynamicSharedMemorySize, ATTN_SMEM);

    prep_G  <<<64, 64>>>(wq, wk);
    prep_Wvo<<<512, 512>>>(wv, wo);
    mma_gemm<true><<<dim3(4, 144), 256, GEMM_SMEM>>>(x, conv_w, conv_b, nullptr, KCONV);
    hq_gemm <<<dim3(1, 1152), 256>>>();
    attn_mma<<<dim3(6, NHEAD, BATCH), 192, ATTN_SMEM>>>();
    mma_gemm<false><<<dim3(4, 144), 256, GEMM_SMEM>>>(nullptr, nullptr, bo, out, EMB_);
}

// round 5
// speedup vs baseline: 2.8966x; 1.0483x over previous
#include <cuda_runtime.h>
#include <math.h>
#include <stdint.h>

// Shapes
#define BATCH   32
#define SLEN    576
#define EMB_    512
#define NHEAD   8
#define HD      64
#define TOK     (BATCH*SLEN) // 18432
#define IMGW    384
#define KCONV   768

// -------- scratch (device globals) --------
__device__ float g_h  [TOK*EMB_];   // patch embeddings
__device__ float g_ctx[TOK*EMB_];   // att @ h
__device__ float g_Gt [HD*HD];      // Gt[n][k] = 0.125 * sum_e wq[e,k]*wk[e,n]
__device__ float g_WvoT[EMB_*EMB_];

// ---------------- tf32 helpers ----------------
__device__ __forceinline__ uint32_t f2tf(float x) {
    uint32_t r; asm("cvt.rna.tf32.f32 %0, %1;" : "=r"(r) : "f"(x)); return r;
}
__device__ __forceinline__ void mma_tf32(float* c, const uint32_t* a, uint32_t b0, uint32_t b1) {
    asm volatile(
        "mma.sync.aligned.m16n8k8.row.col.f32.tf32.tf32.f32 "
        "{%0,%1,%2,%3}, {%4,%5,%6,%7}, {%8,%9}, {%0,%1,%2,%3};\n"
        : "+f"(c[0]), "+f"(c[1]), "+f"(c[2]), "+f"(c[3])
        : "r"(a[0]), "r"(a[1]), "r"(a[2]), "r"(a[3]), "r"(b0), "r"(b1));
}
__device__ __forceinline__ void cp_async16(void* smem, const void* gmem) {
    uint32_t s = (uint32_t)__cvta_generic_to_shared(smem);
    asm volatile("cp.async.cg.shared.global [%0], [%1], 16;\n" :: "r"(s), "l"(gmem));
}
#define CP_COMMIT() asm volatile("cp.async.commit_group;\n")
#define CP_WAIT(n)  asm volatile("cp.async.wait_group %0;\n" :: "n"(n))

// =================================================================
// Weight folding preps (tiny)
// =================================================================
__global__ void prep_G(const float* __restrict__ wq, const float* __restrict__ wk) {
    int dp = blockIdx.x, d = threadIdx.x;
    float s = 0.f;
    #pragma unroll 8
    for (int e = 0; e < 64; e++) s += wq[e*64 + d] * wk[e*64 + dp];
    g_Gt[dp*64 + d] = 0.125f * s;
}
__global__ void prep_Wvo(const float* __restrict__ wv, const float* __restrict__ wo) {
    int f = blockIdx.x, hd = threadIdx.x;
    int h = hd >> 6, d = hd & 63;
    float s = 0.f;
    #pragma unroll 8
    for (int e = 0; e < 64; e++) s += wv[e*64 + d] * wo[(size_t)f*512 + h*64 + e];
    g_WvoT[(size_t)f*512 + hd] = s;
}

// =================================================================
// tf32 MMA GEMM: C[m][n] = A[m][:] . B[n][:] + bias[n]
//   BM=128 BN=128 BK=32, 256 thr (8 warps, 2x4), warp tile 64x32.
// =================================================================
#define GEMM_SMEM (2*128*36*2*4)   // 73728 B

template<bool CONV>
__global__ __launch_bounds__(256) void mma_gemm(const float* __restrict__ Ain,
                                                const float* __restrict__ Bin,
                                                const float* __restrict__ bias,
                                                float* __restrict__ Cout, int K) {
    extern __shared__ float sm[];
    float* As = sm;                 // [2][128][36]
    float* Bs = sm + 2*128*36;      // [2][128][36]

    const int tid = threadIdx.x;
    const int lane = tid & 31;
    const int w = tid >> 5, wm = w & 1, wn = w >> 1;
    const int g = lane >> 2, tig = lane & 3;
    const int m0 = blockIdx.y * 128, n0 = blockIdx.x * 128;

    const float* A = CONV ? Ain : g_ctx;
    const float* B = CONV ? Bin : g_WvoT;

    int lrow[4], lkc[4];
    const float* abase[4];
    const float* bbase[4];
    #pragma unroll
    for (int i = 0; i < 4; i++) {
        int v = tid + i*256;
        int row = v >> 3, kc = v & 7;
        lrow[i] = row; lkc[i] = kc;
        if (CONV) {
            int m = m0 + row;
            int bb = m / 576, p = m % 576;
            int py = p / 24, px = p % 24;
            abase[i] = A + (size_t)bb*3*IMGW*IMGW + (size_t)(py*16)*IMGW + px*16;
        } else {
            abase[i] = A + (size_t)(m0 + row)*512 + kc*4;
        }
        bbase[i] = B + (size_t)(n0 + row)*K + kc*4;
    }

    auto load_tiles = [&](int buf, int k0) {
        #pragma unroll
        for (int i = 0; i < 4; i++) {
            const float* ga;
            if (CONV) {
                int kg = k0 + lkc[i]*4;
                int c = kg >> 8, rem = kg & 255;
                int dy = rem >> 4, dx = rem & 15;
                ga = abase[i] + (size_t)c*(IMGW*IMGW) + dy*IMGW + dx;
            } else {
                ga = abase[i] + k0;
            }
            cp_async16(&As[buf*4608 + lrow[i]*36 + lkc[i]*4], ga);
            cp_async16(&Bs[buf*4608 + lrow[i]*36 + lkc[i]*4], bbase[i] + k0);
        }
    };

    float acc[4][4][4] = {};

    load_tiles(0, 0);
    CP_COMMIT();
    const int nk = K / 32;
    for (int t = 0; t < nk; t++) {
        int buf = t & 1;
        if (t + 1 < nk) load_tiles(buf ^ 1, (t+1)*32);
        CP_COMMIT();
        CP_WAIT(1);
        __syncthreads();

        const float* Ab = &As[buf*4608];
        const float* Bb = &Bs[buf*4608];
        #pragma unroll
        for (int ks = 0; ks < 4; ks++) {
            int k = ks * 8;
            uint32_t af[4][4], bf[4][2];
            #pragma unroll
            for (int i = 0; i < 4; i++) {
                int r = wm*64 + i*16 + g;
                af[i][0] = f2tf(Ab[(r  )*36 + k + tig]);
                af[i][1] = f2tf(Ab[(r+8)*36 + k + tig]);
                af[i][2] = f2tf(Ab[(r  )*36 + k + tig + 4]);
                af[i][3] = f2tf(Ab[(r+8)*36 + k + tig + 4]);
            }
            #pragma unroll
            for (int j = 0; j < 4; j++) {
                int n = wn*32 + j*8 + g;
                bf[j][0] = f2tf(Bb[n*36 + k + tig]);
                bf[j][1] = f2tf(Bb[n*36 + k + tig + 4]);
            }
            #pragma unroll
            for (int i = 0; i < 4; i++)
                #pragma unroll
                for (int j = 0; j < 4; j++)
                    mma_tf32(acc[i][j], af[i], bf[j][0], bf[j][1]);
        }
        __syncthreads();
    }

    float* C = CONV ? g_h : Cout;
    #pragma unroll
    for (int i = 0; i < 4; i++) {
        int r = m0 + wm*64 + i*16 + g;
        #pragma unroll
        for (int j = 0; j < 4; j++) {
            int cc = n0 + wn*32 + j*8 + tig*2;
            float2 v0 = make_float2(acc[i][j][0] + bias[cc], acc[i][j][1] + bias[cc+1]);
            float2 v1 = make_float2(acc[i][j][2] + bias[cc], acc[i][j][3] + bias[cc+1]);
            *(float2*)&C[(size_t)r*512 + cc] = v0;
            *(float2*)&C[(size_t)(r+8)*512 + cc] = v1;
        }
    }
}

// =================================================================
// Flash attention, tf32 MMA, fused Q-projection.
//   Block = 96 q-rows (6 warps x 16), head, batch.
//   Prologue: Q = H @ G via MMA (G shared across heads), stored as
//   tf32 bits in smem.  KV tiles converted to tf32 bits once per tile;
//   P stored as tf32 bits -> hot loops have zero cvt.
// =================================================================
#define ATS 72
#define ATTN_SMEM ((96*ATS + 2*64*ATS + 96*ATS)*4)   // 92160 B

__global__ __launch_bounds__(192) void attn_mma() {
    extern __shared__ float sm[];
    float* Qs  = sm;                    // [96][72]: G (rows 0-63) then Q bits
    float* KVs = Qs + 96*ATS;           // [2][64][72] raw -> tf32 bits in place
    float* Ps  = KVs + 2*64*ATS;        // [96][72]: H tile, then P bits
    uint32_t* Qb = (uint32_t*)Qs;
    uint32_t* Pb = (uint32_t*)Ps;

    const int qt = blockIdx.x, hh = blockIdx.y, b = blockIdx.z;
    const int tid = threadIdx.x;
    const int w = tid >> 5, lane = tid & 31;
    const int g = lane >> 2, tig = lane & 3;
    const size_t rowbase = (size_t)(b*SLEN)*EMB_ + hh*HD;
    const int r0 = w*16 + g, r1 = r0 + 8;

    auto loadKV = [&](int buf, int kt) {
        const float* kb = g_h + rowbase + (size_t)(kt*64)*EMB_;
        for (int v = tid; v < 64*16; v += 192) {
            int r = v >> 4, cq = (v & 15) * 4;
            cp_async16(&KVs[buf*64*ATS + r*ATS + cq], kb + (size_t)r*EMB_ + cq);
        }
    };

    // ---- prologue loads: KV tile 0, H tile (->Ps), G (->Qs rows 0-63) ----
    loadKV(0, 0);
    {
        const float* hb = g_h + rowbase + (size_t)(qt*96)*EMB_;
        for (int v = tid; v < 96*16; v += 192) {
            int r = v >> 4, cq = (v & 15) * 4;
            cp_async16(&Ps[r*ATS + cq], hb + (size_t)r*EMB_ + cq);
        }
        for (int v = tid; v < 64*16; v += 192) {
            int r = v >> 4, cq = (v & 15) * 4;
            cp_async16(&Qs[r*ATS + cq], g_Gt + r*64 + cq);
        }
    }
    CP_COMMIT();
    CP_WAIT(0);
    __syncthreads();

    // ---- Q = H @ G   (q[r][n] = sum_k H[r][k]*Gt[n][k]) ----
    {
        float qc[8][4] = {};
        #pragma unroll
        for (int ks = 0; ks < 8; ks++) {
            int k = ks*8;
            uint32_t ha[4];
            ha[0] = f2tf(Ps[r0*ATS + k + tig]);
            ha[1] = f2tf(Ps[r1*ATS + k + tig]);
            ha[2] = f2tf(Ps[r0*ATS + k + tig + 4]);
            ha[3] = f2tf(Ps[r1*ATS + k + tig + 4]);
            #pragma unroll
            for (int j = 0; j < 8; j++) {
                int n = j*8 + g;
                uint32_t b0 = f2tf(Qs[n*ATS + k + tig]);
                uint32_t b1 = f2tf(Qs[n*ATS + k + tig + 4]);
                mma_tf32(qc[j], ha, b0, b1);
            }
        }
        __syncthreads();   // all warps done reading G (Qs) and H (Ps)
        #pragma unroll
        for (int j = 0; j < 8; j++) {
            Qb[r0*ATS + j*8 + tig*2    ] = f2tf(qc[j][0]);
            Qb[r0*ATS + j*8 + tig*2 + 1] = f2tf(qc[j][1]);
            Qb[r1*ATS + j*8 + tig*2    ] = f2tf(qc[j][2]);
            Qb[r1*ATS + j*8 + tig*2 + 1] = f2tf(qc[j][3]);
        }
        __syncwarp();      // aq reads only this warp's rows
    }

    // Q fragments register-resident for all 8 k-steps (already tf32 bits)
    uint32_t aq[8][4];
    #pragma unroll
    for (int ks = 0; ks < 8; ks++) {
        int k = ks*8;
        aq[ks][0] = Qb[r0*ATS + k + tig];
        aq[ks][1] = Qb[r1*ATS + k + tig];
        aq[ks][2] = Qb[r0*ATS + k + tig + 4];
        aq[ks][3] = Qb[r1*ATS + k + tig + 4];
    }

    float oacc[8][4] = {};
    float m0r = -3.0e38f, m1r = -3.0e38f, l0 = 0.f, l1 = 0.f;

    for (int kt = 0; kt < 9; kt++) {
        int buf = kt & 1;
        CP_WAIT(0);
        __syncthreads();                      // KV[buf] raw floats ready

        if (kt + 1 < 9) { loadKV(buf ^ 1, kt + 1); CP_COMMIT(); }

        // ---- convert KV[buf] to tf32 bits in place (once per tile) ----
        float* KVf = &KVs[buf*64*ATS];
        uint32_t* KB = (uint32_t*)KVf;
        for (int v = tid; v < 64*16; v += 192) {
            int r = v >> 4, c = (v & 15) * 4;
            float4 f = *(float4*)&KVf[r*ATS + c];
            uint4 u;
            u.x = f2tf(f.x); u.y = f2tf(f.y); u.z = f2tf(f.z); u.w = f2tf(f.w);
            *(uint4*)&KB[r*ATS + c] = u;
        }
        __syncthreads();

        // ---- S = Q K^T ----
        float sacc[8][4] = {};
        #pragma unroll
        for (int ks = 0; ks < 8; ks++) {
            int k = ks*8;
            uint32_t bf[8][2];
            #pragma unroll
            for (int j = 0; j < 8; j++) {
                int l = j*8 + g;
                bf[j][0] = KB[l*ATS + k + tig];
                bf[j][1] = KB[l*ATS + k + tig + 4];
            }
            #pragma unroll
            for (int j = 0; j < 8; j++)
                mma_tf32(sacc[j], aq[ks], bf[j][0], bf[j][1]);
        }

        // ---- online softmax (rows r0, r1 per thread-quad) ----
        float mx0 = -3.0e38f, mx1 = -3.0e38f;
        #pragma unroll
        for (int j = 0; j < 8; j++) {
            mx0 = fmaxf(mx0, fmaxf(sacc[j][0], sacc[j][1]));
            mx1 = fmaxf(mx1, fmaxf(sacc[j][2], sacc[j][3]));
        }
        mx0 = fmaxf(mx0, __shfl_xor_sync(0xffffffffu, mx0, 1));
        mx0 = fmaxf(mx0, __shfl_xor_sync(0xffffffffu, mx0, 2));
        mx1 = fmaxf(mx1, __shfl_xor_sync(0xffffffffu, mx1, 1));
        mx1 = fmaxf(mx1, __shfl_xor_sync(0xffffffffu, mx1, 2));

        float mn0 = fmaxf(m0r, mx0), mn1 = fmaxf(m1r, mx1);
        float al0 = __expf(m0r - mn0), al1 = __expf(m1r - mn1);
        m0r = mn0; m1r = mn1;

        float s0 = 0.f, s1 = 0.f;
        #pragma unroll
        for (int j = 0; j < 8; j++) {
            float p0 = __expf(sacc[j][0] - mn0);
            float p1 = __expf(sacc[j][1] - mn0);
            float p2 = __expf(sacc[j][2] - mn1);
            float p3 = __expf(sacc[j][3] - mn1);
            s0 += p0 + p1; s1 += p2 + p3;
            Pb[r0*ATS + j*8 + tig*2    ] = f2tf(p0);
            Pb[r0*ATS + j*8 + tig*2 + 1] = f2tf(p1);
            Pb[r1*ATS + j*8 + tig*2    ] = f2tf(p2);
            Pb[r1*ATS + j*8 + tig*2 + 1] = f2tf(p3);
        }
        s0 += __shfl_xor_sync(0xffffffffu, s0, 1);
        s0 += __shfl_xor_sync(0xffffffffu, s0, 2);
        s1 += __shfl_xor_sync(0xffffffffu, s1, 1);
        s1 += __shfl_xor_sync(0xffffffffu, s1, 2);
        l0 = l0*al0 + s0; l1 = l1*al1 + s1;
        #pragma unroll
        for (int j = 0; j < 8; j++) {
            oacc[j][0] *= al0; oacc[j][1] *= al0;
            oacc[j][2] *= al1; oacc[j][3] *= al1;
        }
        __syncwarp();   // P rows of this warp written by this warp only

        // ---- O += P V  (V == KB, tf32 bits) ----
        #pragma unroll
        for (int ks = 0; ks < 8; ks++) {
            int k = ks*8;
            uint32_t ap[4];
            ap[0] = Pb[r0*ATS + k + tig];
            ap[1] = Pb[r1*ATS + k + tig];
            ap[2] = Pb[r0*ATS + k + tig + 4];
            ap[3] = Pb[r1*ATS + k + tig + 4];
            #pragma unroll
            for (int j = 0; j < 8; j++) {
                int d = j*8 + g;
                uint32_t b0 = KB[(k + tig    )*ATS + d];
                uint32_t b1 = KB[(k + tig + 4)*ATS + d];
                mma_tf32(oacc[j], ap, b0, b1);
            }
        }
    }

    float inv0 = 1.0f / l0, inv1 = 1.0f / l1;
    float* ob = g_ctx + rowbase + (size_t)(qt*96)*EMB_;
    #pragma unroll
    for (int j = 0; j < 8; j++) {
        int d = j*8 + tig*2;
        *(float2*)&ob[(size_t)r0*EMB_ + d] = make_float2(oacc[j][0]*inv0, oacc[j][1]*inv0);
        *(float2*)&ob[(size_t)r1*EMB_ + d] = make_float2(oacc[j][2]*inv1, oacc[j][3]*inv1);
    }
}

// =================================================================
extern "C" void kernel_launch(void* const* d_in, const int* in_sizes, int n_in,
                              void* d_out, int out_size) {
    (void)in_sizes; (void)n_in; (void)out_size;
    const float* x      = (const float*)d_in[0];
    const float* conv_w = (const float*)d_in[1];
    const float* conv_b = (const float*)d_in[2];
    const float* wq     = (const float*)d_in[3];
    const float* wk     = (const float*)d_in[4];
    const float* wv     = (const float*)d_in[5];
    const float* wo     = (const float*)d_in[6];
    const float* bo     = (const float*)d_in[7];
    float* out = (float*)d_out;

    cudaFuncSetAttribute(mma_gemm<true>,  cudaFuncAttributeMaxDynamicSharedMemorySize, GEMM_SMEM);
    cudaFuncSetAttribute(mma_gemm<false>, cudaFuncAttributeMaxDynamicSharedMemorySize, GEMM_SMEM);
    cudaFuncSetAttribute(attn_mma, cudaFuncAttributeMaxDynamicSharedMemorySize, ATTN_SMEM);

    prep_G  <<<64, 64>>>(wq, wk);
    prep_Wvo<<<512, 512>>>(wv, wo);
    mma_gemm<true><<<dim3(4, 144), 256, GEMM_SMEM>>>(x, conv_w, conv_b, nullptr, KCONV);
    attn_mma<<<dim3(6, NHEAD, BATCH), 192, ATTN_SMEM>>>();
    mma_gemm<false><<<dim3(4, 144), 256, GEMM_SMEM>>>(nullptr, nullptr, bo, out, EMB_);
}

// round 6
// speedup vs baseline: 3.0587x; 1.0559x over previous
#include <cuda_runtime.h>
#include <math.h>
#include <stdint.h>

// Shapes
#define BATCH   32
#define SLEN    576
#define EMB_    512
#define NHEAD   8
#define HD      64
#define TOK     (BATCH*SLEN) // 18432
#define IMGW    384
#define KCONV   768

// -------- scratch (device globals) --------
__device__ float g_h  [TOK*EMB_];   // patch embeddings
__device__ float g_ctx[TOK*EMB_];   // att @ h
__device__ float g_Gt [HD*HD];      // Gt[n][k] = 0.125 * sum_e wq[e,k]*wk[e,n]
__device__ float g_WvoT[EMB_*EMB_];

// ---------------- tf32 helpers ----------------
__device__ __forceinline__ uint32_t f2tf(float x) {
    uint32_t r; asm("cvt.rna.tf32.f32 %0, %1;" : "=r"(r) : "f"(x)); return r;
}
__device__ __forceinline__ void mma_tf32(float* c, const uint32_t* a, uint32_t b0, uint32_t b1) {
    asm volatile(
        "mma.sync.aligned.m16n8k8.row.col.f32.tf32.tf32.f32 "
        "{%0,%1,%2,%3}, {%4,%5,%6,%7}, {%8,%9}, {%0,%1,%2,%3};\n"
        : "+f"(c[0]), "+f"(c[1]), "+f"(c[2]), "+f"(c[3])
        : "r"(a[0]), "r"(a[1]), "r"(a[2]), "r"(a[3]), "r"(b0), "r"(b1));
}
__device__ __forceinline__ void cp_async16(void* smem, const void* gmem) {
    uint32_t s = (uint32_t)__cvta_generic_to_shared(smem);
    asm volatile("cp.async.cg.shared.global [%0], [%1], 16;\n" :: "r"(s), "l"(gmem));
}
#define CP_COMMIT() asm volatile("cp.async.commit_group;\n")
#define CP_WAIT(n)  asm volatile("cp.async.wait_group %0;\n" :: "n"(n))

// =================================================================
// Weight folding preps (tiny)
// =================================================================
__global__ void prep_G(const float* __restrict__ wq, const float* __restrict__ wk) {
    int dp = blockIdx.x, d = threadIdx.x;
    float s = 0.f;
    #pragma unroll 8
    for (int e = 0; e < 64; e++) s += wq[e*64 + d] * wk[e*64 + dp];
    g_Gt[dp*64 + d] = 0.125f * s;
}
__global__ void prep_Wvo(const float* __restrict__ wv, const float* __restrict__ wo) {
    int f = blockIdx.x, hd = threadIdx.x;
    int h = hd >> 6, d = hd & 63;
    float s = 0.f;
    #pragma unroll 8
    for (int e = 0; e < 64; e++) s += wv[e*64 + d] * wo[(size_t)f*512 + h*64 + e];
    g_WvoT[(size_t)f*512 + hd] = s;
}

// =================================================================
// tf32 MMA GEMM (unchanged): C = A.B^T + bias, BM=BN=128, BK=32
// =================================================================
#define GEMM_SMEM (2*128*36*2*4)   // 73728 B

template<bool CONV>
__global__ __launch_bounds__(256) void mma_gemm(const float* __restrict__ Ain,
                                                const float* __restrict__ Bin,
                                                const float* __restrict__ bias,
                                                float* __restrict__ Cout, int K) {
    extern __shared__ float sm[];
    float* As = sm;
    float* Bs = sm + 2*128*36;

    const int tid = threadIdx.x;
    const int lane = tid & 31;
    const int w = tid >> 5, wm = w & 1, wn = w >> 1;
    const int g = lane >> 2, tig = lane & 3;
    const int m0 = blockIdx.y * 128, n0 = blockIdx.x * 128;

    const float* A = CONV ? Ain : g_ctx;
    const float* B = CONV ? Bin : g_WvoT;

    int lrow[4], lkc[4];
    const float* abase[4];
    const float* bbase[4];
    #pragma unroll
    for (int i = 0; i < 4; i++) {
        int v = tid + i*256;
        int row = v >> 3, kc = v & 7;
        lrow[i] = row; lkc[i] = kc;
        if (CONV) {
            int m = m0 + row;
            int bb = m / 576, p = m % 576;
            int py = p / 24, px = p % 24;
            abase[i] = A + (size_t)bb*3*IMGW*IMGW + (size_t)(py*16)*IMGW + px*16;
        } else {
            abase[i] = A + (size_t)(m0 + row)*512 + kc*4;
        }
        bbase[i] = B + (size_t)(n0 + row)*K + kc*4;
    }

    auto load_tiles = [&](int buf, int k0) {
        #pragma unroll
        for (int i = 0; i < 4; i++) {
            const float* ga;
            if (CONV) {
                int kg = k0 + lkc[i]*4;
                int c = kg >> 8, rem = kg & 255;
                int dy = rem >> 4, dx = rem & 15;
                ga = abase[i] + (size_t)c*(IMGW*IMGW) + dy*IMGW + dx;
            } else {
                ga = abase[i] + k0;
            }
            cp_async16(&As[buf*4608 + lrow[i]*36 + lkc[i]*4], ga);
            cp_async16(&Bs[buf*4608 + lrow[i]*36 + lkc[i]*4], bbase[i] + k0);
        }
    };

    float acc[4][4][4] = {};

    load_tiles(0, 0);
    CP_COMMIT();
    const int nk = K / 32;
    for (int t = 0; t < nk; t++) {
        int buf = t & 1;
        if (t + 1 < nk) load_tiles(buf ^ 1, (t+1)*32);
        CP_COMMIT();
        CP_WAIT(1);
        __syncthreads();

        const float* Ab = &As[buf*4608];
        const float* Bb = &Bs[buf*4608];
        #pragma unroll
        for (int ks = 0; ks < 4; ks++) {
            int k = ks * 8;
            uint32_t af[4][4], bf[4][2];
            #pragma unroll
            for (int i = 0; i < 4; i++) {
                int r = wm*64 + i*16 + g;
                af[i][0] = f2tf(Ab[(r  )*36 + k + tig]);
                af[i][1] = f2tf(Ab[(r+8)*36 + k + tig]);
                af[i][2] = f2tf(Ab[(r  )*36 + k + tig + 4]);
                af[i][3] = f2tf(Ab[(r+8)*36 + k + tig + 4]);
            }
            #pragma unroll
            for (int j = 0; j < 4; j++) {
                int n = wn*32 + j*8 + g;
                bf[j][0] = f2tf(Bb[n*36 + k + tig]);
                bf[j][1] = f2tf(Bb[n*36 + k + tig + 4]);
            }
            #pragma unroll
            for (int i = 0; i < 4; i++)
                #pragma unroll
                for (int j = 0; j < 4; j++)
                    mma_tf32(acc[i][j], af[i], bf[j][0], bf[j][1]);
        }
        __syncthreads();
    }

    float* C = CONV ? g_h : Cout;
    #pragma unroll
    for (int i = 0; i < 4; i++) {
        int r = m0 + wm*64 + i*16 + g;
        #pragma unroll
        for (int j = 0; j < 4; j++) {
            int cc = n0 + wn*32 + j*8 + tig*2;
            float2 v0 = make_float2(acc[i][j][0] + bias[cc], acc[i][j][1] + bias[cc+1]);
            float2 v1 = make_float2(acc[i][j][2] + bias[cc], acc[i][j][3] + bias[cc+1]);
            *(float2*)&C[(size_t)r*512 + cc] = v0;
            *(float2*)&C[(size_t)(r+8)*512 + cc] = v1;
        }
    }
}

// =================================================================
// Flash attention, tf32 MMA, fused Q-projection, N-split warps.
//   Block = 96 q-rows, 6 warps as 3(wm) x 2(wn); warp tile 32x32.
//   B-fragments (K and V) loaded per wn-half only -> 2x less LDS.
//   Softmax row stats combined across wn pair via tiny smem arrays.
//   P overlays the Q-bits smem region (Q lives in registers).
// =================================================================
#define ATS 72
// R1 96x72 | KV 2x64x72 | Msm 96x2 | Ssm 96x2
#define ATTN_SMEM ((96*ATS + 2*64*ATS + 96*2 + 96*2)*4)   // 66048 B

__global__ __launch_bounds__(192, 2) void attn_mma() {
    extern __shared__ float sm[];
    float* R1  = sm;                     // [96][72]: H -> Q bits -> P bits
    float* KVs = sm + 96*ATS;            // [2][64][72]; buf1 holds G in prologue
    float* Msm = KVs + 2*64*ATS;         // [96][2] partial row max
    float* Ssm = Msm + 96*2;             // [96][2] partial row sum
    uint32_t* Rb = (uint32_t*)R1;

    const int qt = blockIdx.x, hh = blockIdx.y, b = blockIdx.z;
    const int tid = threadIdx.x;
    const int w = tid >> 5, lane = tid & 31;
    const int wm = w >> 1, wn = w & 1;
    const int g = lane >> 2, tig = lane & 3;
    const size_t rowbase = (size_t)(b*SLEN)*EMB_ + hh*HD;
    const int rr[2] = { wm*32 + g, wm*32 + 16 + g };   // m-tile base rows (+8 pair)

    auto loadKV = [&](int buf, int kt) {
        const float* kb = g_h + rowbase + (size_t)(kt*64)*EMB_;
        for (int v = tid; v < 64*16; v += 192) {
            int r = v >> 4, cq = (v & 15) * 4;
            cp_async16(&KVs[buf*64*ATS + r*ATS + cq], kb + (size_t)r*EMB_ + cq);
        }
    };

    // ---- prologue loads: KV tile 0 -> buf0, H -> R1, G -> buf1 ----
    loadKV(0, 0);
    {
        const float* hb = g_h + rowbase + (size_t)(qt*96)*EMB_;
        for (int v = tid; v < 96*16; v += 192) {
            int r = v >> 4, cq = (v & 15) * 4;
            cp_async16(&R1[r*ATS + cq], hb + (size_t)r*EMB_ + cq);
        }
        for (int v = tid; v < 64*16; v += 192) {
            int r = v >> 4, cq = (v & 15) * 4;
            cp_async16(&KVs[64*ATS + r*ATS + cq], g_Gt + r*64 + cq);
        }
    }
    CP_COMMIT();
    CP_WAIT(0);
    __syncthreads();

    // ---- Q = H @ G (warp computes 32 rows x 32 cols) ----
    {
        float qc[2][4][4] = {};
        const float* Gd = &KVs[64*ATS];
        #pragma unroll
        for (int ks = 0; ks < 8; ks++) {
            int k = ks*8;
            uint32_t ha[2][4];
            #pragma unroll
            for (int i = 0; i < 2; i++) {
                ha[i][0] = f2tf(R1[(rr[i]  )*ATS + k + tig]);
                ha[i][1] = f2tf(R1[(rr[i]+8)*ATS + k + tig]);
                ha[i][2] = f2tf(R1[(rr[i]  )*ATS + k + tig + 4]);
                ha[i][3] = f2tf(R1[(rr[i]+8)*ATS + k + tig + 4]);
            }
            #pragma unroll
            for (int j = 0; j < 4; j++) {
                int n = wn*32 + j*8 + g;
                uint32_t b0 = f2tf(Gd[n*ATS + k + tig]);
                uint32_t b1 = f2tf(Gd[n*ATS + k + tig + 4]);
                mma_tf32(qc[0][j], ha[0], b0, b1);
                mma_tf32(qc[1][j], ha[1], b0, b1);
            }
        }
        __syncthreads();   // everyone done reading H (R1) and G (buf1)
        #pragma unroll
        for (int i = 0; i < 2; i++)
            #pragma unroll
            for (int j = 0; j < 4; j++) {
                int cc = wn*32 + j*8 + tig*2;
                Rb[(rr[i]  )*ATS + cc    ] = f2tf(qc[i][j][0]);
                Rb[(rr[i]  )*ATS + cc + 1] = f2tf(qc[i][j][1]);
                Rb[(rr[i]+8)*ATS + cc    ] = f2tf(qc[i][j][2]);
                Rb[(rr[i]+8)*ATS + cc + 1] = f2tf(qc[i][j][3]);
            }
        __syncthreads();   // full-width Q bits visible to both wn warps
    }

    // Q fragments register-resident (full width, both m-tiles)
    uint32_t aq[2][8][4];
    #pragma unroll
    for (int ks = 0; ks < 8; ks++) {
        int k = ks*8;
        #pragma unroll
        for (int i = 0; i < 2; i++) {
            aq[i][ks][0] = Rb[(rr[i]  )*ATS + k + tig];
            aq[i][ks][1] = Rb[(rr[i]+8)*ATS + k + tig];
            aq[i][ks][2] = Rb[(rr[i]  )*ATS + k + tig + 4];
            aq[i][ks][3] = Rb[(rr[i]+8)*ATS + k + tig + 4];
        }
    }

    float oacc[2][4][4] = {};
    float m_[2][2], l_[2][2];
    #pragma unroll
    for (int i = 0; i < 2; i++) { m_[i][0] = m_[i][1] = -3.0e38f; l_[i][0] = l_[i][1] = 0.f; }

    for (int kt = 0; kt < 9; kt++) {
        int buf = kt & 1;
        CP_WAIT(0);
        __syncthreads();                      // KV[buf] raw floats ready

        if (kt + 1 < 9) { loadKV(buf ^ 1, kt + 1); CP_COMMIT(); }

        // ---- convert KV[buf] to tf32 bits in place ----
        float* KVf = &KVs[buf*64*ATS];
        uint32_t* KB = (uint32_t*)KVf;
        for (int v = tid; v < 64*16; v += 192) {
            int r = v >> 4, c = (v & 15) * 4;
            float4 f = *(float4*)&KVf[r*ATS + c];
            uint4 u;
            u.x = f2tf(f.x); u.y = f2tf(f.y); u.z = f2tf(f.z); u.w = f2tf(f.w);
            *(uint4*)&KB[r*ATS + c] = u;
        }
        __syncthreads();

        // ---- S = Q K^T  (warp: 32 rows x 32 K-rows) ----
        float sacc[2][4][4] = {};
        #pragma unroll
        for (int ks = 0; ks < 8; ks++) {
            int k = ks*8;
            #pragma unroll
            for (int j = 0; j < 4; j++) {
                int l = wn*32 + j*8 + g;
                uint32_t b0 = KB[l*ATS + k + tig];
                uint32_t b1 = KB[l*ATS + k + tig + 4];
                mma_tf32(sacc[0][j], aq[0][ks], b0, b1);
                mma_tf32(sacc[1][j], aq[1][ks], b0, b1);
            }
        }

        // ---- partial row max (this wn half), quad-reduce, exchange ----
        float pm[2][2];
        #pragma unroll
        for (int i = 0; i < 2; i++) {
            pm[i][0] = fmaxf(fmaxf(sacc[i][0][0], sacc[i][0][1]), fmaxf(sacc[i][1][0], sacc[i][1][1]));
            pm[i][0] = fmaxf(pm[i][0], fmaxf(fmaxf(sacc[i][2][0], sacc[i][2][1]), fmaxf(sacc[i][3][0], sacc[i][3][1])));
            pm[i][1] = fmaxf(fmaxf(sacc[i][0][2], sacc[i][0][3]), fmaxf(sacc[i][1][2], sacc[i][1][3]));
            pm[i][1] = fmaxf(pm[i][1], fmaxf(fmaxf(sacc[i][2][2], sacc[i][2][3]), fmaxf(sacc[i][3][2], sacc[i][3][3])));
            #pragma unroll
            for (int r = 0; r < 2; r++) {
                pm[i][r] = fmaxf(pm[i][r], __shfl_xor_sync(0xffffffffu, pm[i][r], 1));
                pm[i][r] = fmaxf(pm[i][r], __shfl_xor_sync(0xffffffffu, pm[i][r], 2));
            }
        }
        if (tig == 0) {
            #pragma unroll
            for (int i = 0; i < 2; i++) {
                Msm[(rr[i]  )*2 + wn] = pm[i][0];
                Msm[(rr[i]+8)*2 + wn] = pm[i][1];
            }
        }
        __syncthreads();

        // ---- combine max, compute alpha ----
        float alpha[2][2];
        #pragma unroll
        for (int i = 0; i < 2; i++) {
            #pragma unroll
            for (int r = 0; r < 2; r++) {
                int row = rr[i] + r*8;
                float mt = fmaxf(Msm[row*2], Msm[row*2 + 1]);
                float mnew = fmaxf(m_[i][r], mt);
                alpha[i][r] = __expf(m_[i][r] - mnew);
                m_[i][r] = mnew;
            }
        }

        // ---- p = exp(s - m), store to R1, partial sums, exchange ----
        float psum[2][2] = {};
        #pragma unroll
        for (int i = 0; i < 2; i++)
            #pragma unroll
            for (int j = 0; j < 4; j++) {
                int cc = wn*32 + j*8 + tig*2;
                float p0 = __expf(sacc[i][j][0] - m_[i][0]);
                float p1 = __expf(sacc[i][j][1] - m_[i][0]);
                float p2 = __expf(sacc[i][j][2] - m_[i][1]);
                float p3 = __expf(sacc[i][j][3] - m_[i][1]);
                psum[i][0] += p0 + p1;
                psum[i][1] += p2 + p3;
                Rb[(rr[i]  )*ATS + cc    ] = f2tf(p0);
                Rb[(rr[i]  )*ATS + cc + 1] = f2tf(p1);
                Rb[(rr[i]+8)*ATS + cc    ] = f2tf(p2);
                Rb[(rr[i]+8)*ATS + cc + 1] = f2tf(p3);
            }
        #pragma unroll
        for (int i = 0; i < 2; i++)
            #pragma unroll
            for (int r = 0; r < 2; r++) {
                psum[i][r] += __shfl_xor_sync(0xffffffffu, psum[i][r], 1);
                psum[i][r] += __shfl_xor_sync(0xffffffffu, psum[i][r], 2);
            }
        if (tig == 0) {
            #pragma unroll
            for (int i = 0; i < 2; i++) {
                Ssm[(rr[i]  )*2 + wn] = psum[i][0];
                Ssm[(rr[i]+8)*2 + wn] = psum[i][1];
            }
        }
        __syncthreads();   // P full width + sums visible

        #pragma unroll
        for (int i = 0; i < 2; i++) {
            #pragma unroll
            for (int r = 0; r < 2; r++) {
                int row = rr[i] + r*8;
                l_[i][r] = l_[i][r]*alpha[i][r] + Ssm[row*2] + Ssm[row*2 + 1];
            }
            #pragma unroll
            for (int j = 0; j < 4; j++) {
                oacc[i][j][0] *= alpha[i][0]; oacc[i][j][1] *= alpha[i][0];
                oacc[i][j][2] *= alpha[i][1]; oacc[i][j][3] *= alpha[i][1];
            }
        }

        // ---- O += P V  (A = P full width from R1, B = V half from KB) ----
        #pragma unroll
        for (int ks = 0; ks < 8; ks++) {
            int k = ks*8;
            uint32_t ap[2][4];
            #pragma unroll
            for (int i = 0; i < 2; i++) {
                ap[i][0] = Rb[(rr[i]  )*ATS + k + tig];
                ap[i][1] = Rb[(rr[i]+8)*ATS + k + tig];
                ap[i][2] = Rb[(rr[i]  )*ATS + k + tig + 4];
                ap[i][3] = Rb[(rr[i]+8)*ATS + k + tig + 4];
            }
            #pragma unroll
            for (int j = 0; j < 4; j++) {
                int d = wn*32 + j*8 + g;
                uint32_t b0 = KB[(k + tig    )*ATS + d];
                uint32_t b1 = KB[(k + tig + 4)*ATS + d];
                mma_tf32(oacc[0][j], ap[0], b0, b1);
                mma_tf32(oacc[1][j], ap[1], b0, b1);
            }
        }
    }

    // ---- epilogue ----
    float* ob = g_ctx + rowbase + (size_t)(qt*96)*EMB_;
    #pragma unroll
    for (int i = 0; i < 2; i++)
        #pragma unroll
        for (int r = 0; r < 2; r++) {
            int row = rr[i] + r*8;
            float inv = 1.0f / l_[i][r];
            #pragma unroll
            for (int j = 0; j < 4; j++) {
                int d = wn*32 + j*8 + tig*2;
                float2 v = make_float2(oacc[i][j][r*2]*inv, oacc[i][j][r*2+1]*inv);
                *(float2*)&ob[(size_t)row*EMB_ + d] = v;
            }
        }
}

// =================================================================
extern "C" void kernel_launch(void* const* d_in, const int* in_sizes, int n_in,
                              void* d_out, int out_size) {
    (void)in_sizes; (void)n_in; (void)out_size;
    const float* x      = (const float*)d_in[0];
    const float* conv_w = (const float*)d_in[1];
    const float* conv_b = (const float*)d_in[2];
    const float* wq     = (const float*)d_in[3];
    const float* wk     = (const float*)d_in[4];
    const float* wv     = (const float*)d_in[5];
    const float* wo     = (const float*)d_in[6];
    const float* bo     = (const float*)d_in[7];
    float* out = (float*)d_out;

    cudaFuncSetAttribute(mma_gemm<true>,  cudaFuncAttributeMaxDynamicSharedMemorySize, GEMM_SMEM);
    cudaFuncSetAttribute(mma_gemm<false>, cudaFuncAttributeMaxDynamicSharedMemorySize, GEMM_SMEM);
    cudaFuncSetAttribute(attn_mma, cudaFuncAttributeMaxDynamicSharedMemorySize, ATTN_SMEM);

    prep_G  <<<64, 64>>>(wq, wk);
    prep_Wvo<<<512, 512>>>(wv, wo);
    mma_gemm<true><<<dim3(4, 144), 256, GEMM_SMEM>>>(x, conv_w, conv_b, nullptr, KCONV);
    attn_mma<<<dim3(6, NHEAD, BATCH), 192, ATTN_SMEM>>>();
    mma_gemm<false><<<dim3(4, 144), 256, GEMM_SMEM>>>(nullptr, nullptr, bo, out, EMB_);
}